// round 7
// baseline (speedup 1.0000x reference)
#include <cuda_runtime.h>
#include <cuda_bf16.h>

// 3x3 PCF shadow via light-space binning:
//  1) histogram pixels into (batch, 64x64 light tile) bins
//  2) exclusive scan -> bin offsets
//  3) scatter {x, y, depth, out_idx} records into bin order
//  4) per-bin block: load 66x66 zbuf tile (halo, clamp folded) to smem; taps = LDS
// Shapes that don't fit the scratch caps fall back to the direct-gather kernel.

#define MAXB   32768          // max bins (N * tiles^2)
#define RECCAP 9437184        // max pixels

struct Params { int S, N, HWK, tilesx, nbins, use_binned; unsigned SS; };
__device__ Params g_p;
__device__ int  g_cnt[MAXB];
__device__ int  g_off[MAXB];
__device__ int  g_cur[MAXB];
__device__ int4 g_rec[RECCAP];

__device__ __forceinline__ float ex2f(float x) {
    float y; asm("ex2.approx.f32 %0, %1;" : "=f"(y) : "f"(x)); return y;
}
__device__ __forceinline__ float rcpf(float x) {
    float y; asm("rcp.approx.f32 %0, %1;" : "=f"(y) : "f"(x)); return y;
}
__device__ __forceinline__ float quad_sum(float p0, float p1, float p2, float p3) {
    float a = p0 * p1, b = p2 * p3;
    return ((p0 + p1) * b + (p2 + p3) * a) * rcpf(a * b);
}
__device__ __forceinline__ float pval(float v, float C, float K) {
    float u = fmaf(-v, K, C);
    u = fminf(u, 30.0f);
    return 1.0f + ex2f(u);
}

// ---------------- pass 0: params + zero histogram ----------------
__global__ void k_init(const int* __restrict__ image_size, int total, int zbuf_total) {
    int t = blockIdx.x * blockDim.x + threadIdx.x;
    for (int i = t; i < MAXB; i += gridDim.x * blockDim.x) g_cnt[i] = 0;
    if (t == 0) {
        int S = *image_size;
        int ok = (S >= 2) && (S <= 16384);
        unsigned SS = ok ? (unsigned)S * (unsigned)S : 1u;
        int N   = (int)((unsigned)zbuf_total / SS);
        if (N < 1) { N = 1; ok = 0; }
        int HWK = total / N;
        if (HWK < 1) { HWK = 1; ok = 0; }
        int tilesx = (S + 63) >> 6;
        long long nb = (long long)N * tilesx * tilesx;
        ok = ok && (nb > 0) && (nb <= MAXB) && (total <= RECCAP)
                && ((long long)N * HWK == (long long)total)
                && ((long long)N * SS == (long long)zbuf_total);
        g_p.S = S; g_p.SS = SS; g_p.N = N; g_p.HWK = HWK;
        g_p.tilesx = tilesx; g_p.nbins = (int)nb; g_p.use_binned = ok ? 1 : 0;
    }
}

// ---------------- pass 1: histogram ----------------
__global__ __launch_bounds__(256) void k_hist(const int* __restrict__ xy, int total) {
    if (!g_p.use_binned) return;
    const int HWK = g_p.HWK, tx = g_p.tilesx, S1 = g_p.S - 1, tpb = tx * tx;
    for (int i = blockIdx.x * blockDim.x + threadIdx.x; i < total;
         i += gridDim.x * blockDim.x) {
        int2 c = __ldg((const int2*)xy + i);
        int x = min(max(c.x, 0), S1);
        int y = min(max(c.y, 0), S1);
        int b = i / HWK;
        atomicAdd(&g_cnt[b * tpb + (y >> 6) * tx + (x >> 6)], 1);
    }
}

// ---------------- pass 2: exclusive scan (single block) ----------------
__global__ __launch_bounds__(256) void k_scan() {
    if (!g_p.use_binned) return;
    __shared__ int buf[256];
    __shared__ int carry;
    const int tid = threadIdx.x;
    if (tid == 0) carry = 0;
    __syncthreads();
    const int nb = g_p.nbins;
    for (int base = 0; base < nb; base += 256) {
        int i = base + tid;
        int v = (i < nb) ? g_cnt[i] : 0;
        buf[tid] = v;
        __syncthreads();
        for (int s = 1; s < 256; s <<= 1) {
            int t2 = (tid >= s) ? buf[tid - s] : 0;
            __syncthreads();
            buf[tid] += t2;
            __syncthreads();
        }
        int excl = buf[tid] - v;
        if (i < nb) { int o = carry + excl; g_off[i] = o; g_cur[i] = o; }
        __syncthreads();
        if (tid == 255) carry += buf[255];
        __syncthreads();
    }
}

// ---------------- pass 3: scatter records ----------------
__global__ __launch_bounds__(256) void k_scatter(const int* __restrict__ xy,
                                                 const float* __restrict__ depth,
                                                 int total) {
    if (!g_p.use_binned) return;
    const int HWK = g_p.HWK, tx = g_p.tilesx, S1 = g_p.S - 1, tpb = tx * tx;
    for (int i = blockIdx.x * blockDim.x + threadIdx.x; i < total;
         i += gridDim.x * blockDim.x) {
        int2 c  = __ldg((const int2*)xy + i);
        float d = __ldg(depth + i);
        int x = min(max(c.x, 0), S1);
        int y = min(max(c.y, 0), S1);
        int b = i / HWK;
        int bin = b * tpb + (y >> 6) * tx + (x >> 6);
        int pos = atomicAdd(&g_cur[bin], 1);
        g_rec[pos] = make_int4(x, y, __float_as_int(d), i);
    }
}

// ---------------- pass 4: per-bin PCF with smem tile ----------------
__global__ __launch_bounds__(256) void k_main(const float* __restrict__ zbuf,
                                              float* __restrict__ out) {
    if (!g_p.use_binned) return;
    __shared__ float tile[66 * 66];
    const int S = g_p.S, tx = g_p.tilesx;
    const unsigned SS = g_p.SS;
    const int tpb = tx * tx;
    const float Kc = 1000.0f * 1.4426950408889634f;

    for (int bin = blockIdx.x; bin < g_p.nbins; bin += gridDim.x) {
        const int cnt = g_cnt[bin];     // uniform within block
        if (cnt == 0) continue;

        const int b   = bin / tpb;
        const int rem = bin - b * tpb;
        const int ty  = rem / tx;
        const int txi = rem - ty * tx;
        const int x0  = txi << 6;
        const int y0  = ty << 6;
        const float* zb = zbuf + (size_t)b * (size_t)SS;

        __syncthreads();                // protect previous iteration's readers
        for (int t = threadIdx.x; t < 66 * 66; t += 256) {
            int r  = t / 66;
            int c2 = t - r * 66;
            int gy = min(max(y0 - 1 + r, 0), S - 1);
            int gx = min(max(x0 - 1 + c2, 0), S - 1);
            tile[t] = __ldg(zb + (size_t)(unsigned)gy * (unsigned)S + gx);
        }
        __syncthreads();

        const int off = g_off[bin];
        for (int i = off + threadIdx.x; i < off + cnt; i += 256) {
            int4 rec = __ldg(&g_rec[i]);
            const int x = rec.x, y = rec.y;
            const float C = (__int_as_float(rec.z) - 0.008f) * Kc;
            // smem col for tap jj: clamp(x+jj,0,S-1) - x0 + 1  (halo holds clamped src)
            int cc0 = max(x - 1, 0) - x0 + 1;
            int cc1 = x - x0 + 1;
            int cc2 = min(x + 1, S - 1) - x0 + 1;
            int rr0 = (max(y - 1, 0) - y0 + 1) * 66;
            int rr1 = (y - y0 + 1) * 66;
            int rr2 = (min(y + 1, S - 1) - y0 + 1) * 66;
            float pv[9];
            pv[0] = pval(tile[rr0 + cc0], C, Kc);
            pv[1] = pval(tile[rr0 + cc1], C, Kc);
            pv[2] = pval(tile[rr0 + cc2], C, Kc);
            pv[3] = pval(tile[rr1 + cc0], C, Kc);
            pv[4] = pval(tile[rr1 + cc1], C, Kc);
            pv[5] = pval(tile[rr1 + cc2], C, Kc);
            pv[6] = pval(tile[rr2 + cc0], C, Kc);
            pv[7] = pval(tile[rr2 + cc1], C, Kc);
            pv[8] = pval(tile[rr2 + cc2], C, Kc);
            float acc = quad_sum(pv[0], pv[1], pv[2], pv[3])
                      + quad_sum(pv[4], pv[5], pv[6], pv[7])
                      + rcpf(pv[8]);
            out[rec.w] = acc * (1.0f / 9.0f);
        }
    }
}

// ---------------- fallback: direct gather (R4 config, 137 us) ----------------
__global__ __launch_bounds__(256) void k_fallback(
    const float* __restrict__ zbuf, const float* __restrict__ depth,
    const int* __restrict__ xy, float* __restrict__ out,
    int total, int zbuf_total)
{
    if (g_p.use_binned) return;
    __shared__ int sm_S, sm_b0, sm_lim;
    __shared__ unsigned sm_SS;

    const int i    = blockIdx.x * blockDim.x + threadIdx.x;
    const int idx0 = 2 * i;

    if (threadIdx.x == 0) {
        int S = g_p.S;
        unsigned SS = (unsigned)S * (unsigned)S;
        int N   = (int)((unsigned)zbuf_total / max(SS, 1u));
        if (N < 1) N = 1;
        int HWK = max(total / N, 1);
        int b0  = (blockIdx.x * blockDim.x * 2) / HWK;
        sm_S = S; sm_SS = SS; sm_b0 = b0; sm_lim = (b0 + 1) * HWK;
    }
    __syncthreads();
    if (idx0 >= total) return;

    const int S = sm_S;
    const unsigned SS = sm_SS;
    const int b0v = sm_b0, lim = sm_lim;
    const bool has2 = (idx0 + 1) < total;
    const float Kc = 1000.0f * 1.4426950408889634f;

    int xs[2], ys[2];
    float C_[2];
    if (has2) {
        int4   cc = __ldg((const int4*)(xy + 2 * idx0));
        float2 dd = __ldg((const float2*)(depth + idx0));
        xs[0] = cc.x; ys[0] = cc.y; xs[1] = cc.z; ys[1] = cc.w;
        C_[0] = (dd.x - 0.008f) * Kc; C_[1] = (dd.y - 0.008f) * Kc;
    } else {
        int2 cc = __ldg((const int2*)(xy + 2 * idx0));
        xs[0] = cc.x; ys[0] = cc.y; xs[1] = 0; ys[1] = 0;
        C_[0] = (__ldg(depth + idx0) - 0.008f) * Kc; C_[1] = 0.0f;
    }

    float acc[2] = {0.0f, 0.0f};
    for (int p = 0; p < 2; ++p) {
        const int idx = idx0 + p;
        if (p == 1 && !has2) break;
        const int b = b0v + (idx >= lim);
        const int x = xs[p], y = ys[p];
        const int xm = max(x - 1, 0), xp = min(x + 1, S - 1);
        const int ym = max(y - 1, 0), yp = min(y + 1, S - 1);
        const float* zb = zbuf + (size_t)b * (size_t)SS;
        const float C = C_[p];
        float a = 0.0f;
        int yy[3] = {ym, y, yp};
        for (int r = 0; r < 3; ++r) {
            const float* rr = zb + (size_t)(unsigned)yy[r] * (unsigned)S;
            a += rcpf(pval(__ldg(rr + xm), C, Kc));
            a += rcpf(pval(__ldg(rr + x ), C, Kc));
            a += rcpf(pval(__ldg(rr + xp), C, Kc));
        }
        acc[p] = a;
    }

    if (has2) {
        float2 o = make_float2(acc[0] * (1.0f / 9.0f), acc[1] * (1.0f / 9.0f));
        *(float2*)(out + idx0) = o;
    } else {
        out[idx0] = acc[0] * (1.0f / 9.0f);
    }
}

extern "C" void kernel_launch(void* const* d_in, const int* in_sizes, int n_in,
                              void* d_out, int out_size) {
    const float* zbuf   = (const float*)d_in[0];
    const float* depth  = (const float*)d_in[1];
    const int*   xy     = (const int*)  d_in[2];
    const int*   imsz   = (const int*)  d_in[3];
    float*       out    = (float*)d_out;

    const int total      = in_sizes[1];
    const int zbuf_total = in_sizes[0];

    k_init<<<64, 256>>>(imsz, total, zbuf_total);
    k_hist<<<2048, 256>>>(xy, total);
    k_scan<<<1, 256>>>();
    k_scatter<<<2048, 256>>>(xy, depth, total);
    k_main<<<8192, 256>>>(zbuf, out);

    const int pairs  = (total + 1) / 2;
    const int blocks = (pairs + 255) / 256;
    k_fallback<<<blocks, 256>>>(zbuf, depth, xy, out, total, zbuf_total);
}

// round 8
// speedup vs baseline: 4.1959x; 4.1959x over previous
#include <cuda_runtime.h>
#include <cuda_bf16.h>

// 3x3 PCF shadow visibility, 4 pixels per thread (max per-thread MLP):
// vis = (1/9) * sum sigmoid((zbuf[b, clamp(y+ii), clamp(x+jj)] - (z - 0.008)) * 1000)

__device__ __forceinline__ float ex2f(float x) {
    float y; asm("ex2.approx.f32 %0, %1;" : "=f"(y) : "f"(x)); return y;
}
__device__ __forceinline__ float rcpf(float x) {
    float y; asm("rcp.approx.f32 %0, %1;" : "=f"(y) : "f"(x)); return y;
}
__device__ __forceinline__ float quad_sum(float p0, float p1, float p2, float p3) {
    float a = p0 * p1, b = p2 * p3;
    return ((p0 + p1) * b + (p2 + p3) * a) * rcpf(a * b);
}
__device__ __forceinline__ float pval(float v, float C, float K) {
    float u = fmaf(-v, K, C);
    u = fminf(u, 30.0f);
    return 1.0f + ex2f(u);
}

__global__ __launch_bounds__(256) void shadow_pcf4_kernel(
    const float* __restrict__ zbuf,       // [N, S, S]
    const float* __restrict__ depth,      // [N, H, W, K]
    const int*   __restrict__ xy,         // [N, H, W, K, 2]
    const int*   __restrict__ image_size, // scalar S (device)
    float*       __restrict__ out,        // [N, H, W, K]
    int total,                            // N*H*W*K
    int zbuf_total)                       // N*S*S
{
    __shared__ int sm_S, sm_b0, sm_lim, sm_hwk;
    __shared__ unsigned sm_SS;

    const int i    = blockIdx.x * blockDim.x + threadIdx.x;
    const int idx0 = 4 * i;

    if (threadIdx.x == 0) {
        int S = *image_size;
        unsigned SS = (unsigned)S * (unsigned)S;
        int N   = (int)((unsigned)zbuf_total / SS);
        if (N < 1) N = 1;
        int HWK = total / N;
        if (HWK < 1) HWK = 1;
        int base = blockIdx.x * blockDim.x * 4;
        int b0 = base / HWK;
        sm_S = S; sm_SS = SS; sm_b0 = b0; sm_hwk = HWK;
        sm_lim = (b0 + 1) * HWK;
    }
    __syncthreads();

    if (idx0 >= total) return;

    const int S       = sm_S;
    const unsigned SS = sm_SS;
    const int b0v     = sm_b0;
    const int lim     = sm_lim;
    const int HWK     = sm_hwk;
    // straddle trick valid when a block (1024 px) spans <= 1 batch boundary
    const bool small_hwk = (HWK < 1024);
    const bool full   = (idx0 + 3) < total;

    const float Kc = 1000.0f * 1.4426950408889634f;

    int xs[4], ys[4];
    float C_[4];
    int np = 4;
    if (full) {
        const int4* xp4 = (const int4*)(xy + 2 * idx0);
        int4 cc0 = __ldg(xp4);
        int4 cc1 = __ldg(xp4 + 1);
        float4 dd = __ldg((const float4*)(depth + idx0));
        xs[0] = cc0.x; ys[0] = cc0.y; xs[1] = cc0.z; ys[1] = cc0.w;
        xs[2] = cc1.x; ys[2] = cc1.y; xs[3] = cc1.z; ys[3] = cc1.w;
        C_[0] = (dd.x - 0.008f) * Kc; C_[1] = (dd.y - 0.008f) * Kc;
        C_[2] = (dd.z - 0.008f) * Kc; C_[3] = (dd.w - 0.008f) * Kc;
    } else {
        np = total - idx0;                 // 1..3
#pragma unroll
        for (int p = 0; p < 4; ++p) {
            if (p < np) {
                int2 cc = __ldg((const int2*)(xy + 2 * (idx0 + p)));
                xs[p] = cc.x; ys[p] = cc.y;
                C_[p] = (__ldg(depth + idx0 + p) - 0.008f) * Kc;
            } else { xs[p] = 0; ys[p] = 0; C_[p] = 0.0f; }
        }
    }

    float acc[4];

    if (((S & 3) == 0) && full && !small_hwk) {
        // ---- fast path: rows 16B-aligned, 4 whole pixels ----
        unsigned off[4][3];                // element offsets into zbuf
        bool d2_[4], d1_[4], lo_[4], hi_[4], nq_[4];

#pragma unroll
        for (int p = 0; p < 4; ++p) {
            const int idx = idx0 + p;
            const int b   = b0v + (idx >= lim);
            const int x = xs[p], y = ys[p];
            const int ym = max(y - 1, 0);
            const int yp = min(y + 1, S - 1);
            const int xi = min(max(x, 1), S - 2);
            const int c0 = xi - 1;
            const int e16 = c0 & ~3;
            const int d   = c0 - e16;      // 0..3
            nq_[p] = (d >= 2);
            d2_[p] = (d & 2) != 0;
            d1_[p] = (d & 1) != 0;
            lo_[p] = (x < 1);
            hi_[p] = (x > S - 2);
            unsigned base = (unsigned)b * SS + (unsigned)e16;
            off[p][0] = base + (unsigned)ym * (unsigned)S;
            off[p][1] = base + (unsigned)y  * (unsigned)S;
            off[p][2] = base + (unsigned)yp * (unsigned)S;
        }

        // Issue ALL 24 gathers before any consumption (max MLP).
        float4 P[4][3];
        float2 Q[4][3];
#pragma unroll
        for (int p = 0; p < 4; ++p)
#pragma unroll
            for (int r = 0; r < 3; ++r)
                P[p][r] = __ldg((const float4*)(zbuf + off[p][r]));
#pragma unroll
        for (int p = 0; p < 4; ++p)
#pragma unroll
            for (int r = 0; r < 3; ++r) {
                Q[p][r] = make_float2(0.0f, 0.0f);
                if (nq_[p]) Q[p][r] = __ldg((const float2*)(zbuf + off[p][r] + 4));
            }

#pragma unroll
        for (int p = 0; p < 4; ++p) {
            const bool d2 = d2_[p], d1 = d1_[p], lo = lo_[p], hi = hi_[p];
            const float C = C_[p];
            float pv[9];
#pragma unroll
            for (int r = 0; r < 3; ++r) {
                float g0 = d2 ? P[p][r].z : P[p][r].x;
                float g1 = d2 ? P[p][r].w : P[p][r].y;
                float g2 = d2 ? Q[p][r].x : P[p][r].z;
                float g3 = d2 ? Q[p][r].y : P[p][r].w;
                float t0 = d1 ? g1 : g0;
                float t1 = d1 ? g2 : g1;
                float t2 = d1 ? g3 : g2;
                float vl = hi ? t1 : t0;
                float vm = lo ? t0 : (hi ? t2 : t1);
                float vr = lo ? t1 : t2;
                pv[3 * r + 0] = pval(vl, C, Kc);
                pv[3 * r + 1] = pval(vm, C, Kc);
                pv[3 * r + 2] = pval(vr, C, Kc);
            }
            acc[p] = quad_sum(pv[0], pv[1], pv[2], pv[3])
                   + quad_sum(pv[4], pv[5], pv[6], pv[7])
                   + rcpf(pv[8]);
        }

        float4 o = make_float4(acc[0] * (1.0f / 9.0f), acc[1] * (1.0f / 9.0f),
                               acc[2] * (1.0f / 9.0f), acc[3] * (1.0f / 9.0f));
        *(float4*)(out + idx0) = o;
    } else {
        // ---- generic path: scalar gathers, rolled ----
        for (int p = 0; p < np; ++p) {
            const int idx = idx0 + p;
            const int b = small_hwk ? (idx / HWK) : (b0v + (idx >= lim));
            const int x = xs[p], y = ys[p];
            const int xm = max(x - 1, 0), xp2 = min(x + 1, S - 1);
            const int ym = max(y - 1, 0), yp2 = min(y + 1, S - 1);
            const float* zb = zbuf + (size_t)b * (size_t)SS;
            const float C = C_[p];
            float a = 0.0f;
            int yy[3] = {ym, y, yp2};
            for (int r = 0; r < 3; ++r) {
                const float* rr = zb + (size_t)(unsigned)yy[r] * (unsigned)S;
                a += rcpf(pval(__ldg(rr + xm),  C, Kc));
                a += rcpf(pval(__ldg(rr + x ),  C, Kc));
                a += rcpf(pval(__ldg(rr + xp2), C, Kc));
            }
            out[idx] = a * (1.0f / 9.0f);
        }
    }
}

extern "C" void kernel_launch(void* const* d_in, const int* in_sizes, int n_in,
                              void* d_out, int out_size) {
    const float* zbuf   = (const float*)d_in[0];
    const float* depth  = (const float*)d_in[1];
    const int*   xy     = (const int*)  d_in[2];
    const int*   imsz   = (const int*)  d_in[3];
    float*       out    = (float*)d_out;

    const int total      = in_sizes[1];
    const int zbuf_total = in_sizes[0];

    const int threads = 256;
    const int quads   = (total + 3) / 4;
    const int blocks  = (quads + threads - 1) / threads;
    shadow_pcf4_kernel<<<blocks, threads>>>(zbuf, depth, xy, imsz, out,
                                            total, zbuf_total);
}

// round 9
// speedup vs baseline: 4.3800x; 1.0439x over previous
#include <cuda_runtime.h>
#include <cuda_bf16.h>
#include <cstdint>

// 3x3 PCF shadow visibility, 2 pixels/thread.
// xy+depth are staged into smem via cp.async.bulk (TMA) to keep their
// streaming traffic out of the L1 sector-fill pipe; zbuf gathers stay LDG.

__device__ __forceinline__ float ex2f(float x) {
    float y; asm("ex2.approx.f32 %0, %1;" : "=f"(y) : "f"(x)); return y;
}
__device__ __forceinline__ float rcpf(float x) {
    float y; asm("rcp.approx.f32 %0, %1;" : "=f"(y) : "f"(x)); return y;
}
__device__ __forceinline__ float quad_sum(float p0, float p1, float p2, float p3) {
    float a = p0 * p1, b = p2 * p3;
    return ((p0 + p1) * b + (p2 + p3) * a) * rcpf(a * b);
}
__device__ __forceinline__ float pval(float v, float C, float K) {
    float u = fmaf(-v, K, C);
    u = fminf(u, 30.0f);
    return 1.0f + ex2f(u);
}

__device__ __forceinline__ uint32_t smem_u32(const void* p) {
    return (uint32_t)__cvta_generic_to_shared(p);
}

#define PX_PER_BLOCK 512   // 256 threads * 2 px

__global__ __launch_bounds__(256) void shadow_pcf2t_kernel(
    const float* __restrict__ zbuf,       // [N, S, S]
    const float* __restrict__ depth,      // [N, H, W, K]
    const int*   __restrict__ xy,         // [N, H, W, K, 2]
    const int*   __restrict__ image_size, // scalar S (device)
    float*       __restrict__ out,        // [N, H, W, K]
    int total,                            // N*H*W*K
    int zbuf_total)                       // N*S*S
{
    __shared__ alignas(16) int   st_xy[PX_PER_BLOCK * 2];   // 4096 B
    __shared__ alignas(16) float st_d[PX_PER_BLOCK];        // 2048 B
    __shared__ alignas(8) unsigned long long mbar;
    __shared__ int sm_S, sm_b0, sm_lim;
    __shared__ unsigned sm_SS;

    const int base  = blockIdx.x * PX_PER_BLOCK;
    const int idx0  = base + 2 * threadIdx.x;
    const bool full_tile = (base + PX_PER_BLOCK) <= total;

    // --- kick off TMA staging ASAP (thread 0), params on thread 32 ---
    if (threadIdx.x == 0) {
        asm volatile("mbarrier.init.shared.b64 [%0], 1;"
                     :: "r"(smem_u32(&mbar)) : "memory");
    }
    if (threadIdx.x == 32) {
        int S = *image_size;
        unsigned SS = (unsigned)S * (unsigned)S;
        int N   = (int)((unsigned)zbuf_total / SS);
        if (N < 1) N = 1;
        int HWK = total / N;
        if (HWK < 1) HWK = 1;
        int b0 = base / HWK;
        sm_S = S; sm_SS = SS; sm_b0 = b0;
        sm_lim = (b0 + 1) * HWK;
    }
    __syncthreads();
    if (threadIdx.x == 0 && full_tile) {
        asm volatile("fence.proxy.async.shared::cta;" ::: "memory");
        const uint32_t tx = PX_PER_BLOCK * 8 + PX_PER_BLOCK * 4;
        asm volatile("mbarrier.arrive.expect_tx.shared.b64 _, [%0], %1;"
                     :: "r"(smem_u32(&mbar)), "r"(tx) : "memory");
        asm volatile(
            "cp.async.bulk.shared::cta.global.mbarrier::complete_tx::bytes "
            "[%0], [%1], %2, [%3];"
            :: "r"(smem_u32(st_xy)), "l"(xy + 2 * base),
               "r"((uint32_t)(PX_PER_BLOCK * 8)), "r"(smem_u32(&mbar))
            : "memory");
        asm volatile(
            "cp.async.bulk.shared::cta.global.mbarrier::complete_tx::bytes "
            "[%0], [%1], %2, [%3];"
            :: "r"(smem_u32(st_d)), "l"(depth + base),
               "r"((uint32_t)(PX_PER_BLOCK * 4)), "r"(smem_u32(&mbar))
            : "memory");
    }

    if (idx0 >= total) return;

    const int S       = sm_S;
    const unsigned SS = sm_SS;
    const int b0v     = sm_b0;
    const int lim     = sm_lim;
    const bool has2   = (idx0 + 1) < total;
    const float Kc = 1000.0f * 1.4426950408889634f;

    int xs[2], ys[2];
    float C_[2];

    if (full_tile) {
        // wait for TMA completion (phase 0)
        uint32_t mb = smem_u32(&mbar);
        uint32_t done;
        asm volatile(
            "{\n\t.reg .pred p;\n\t"
            "mbarrier.try_wait.parity.acquire.cta.shared::cta.b64 p, [%1], 0;\n\t"
            "selp.b32 %0, 1, 0, p;\n\t}"
            : "=r"(done) : "r"(mb) : "memory");
        if (!done) {
            asm volatile(
                "{\n\t.reg .pred P1;\n\t"
                "W_%=:\n\t"
                "mbarrier.try_wait.parity.acquire.cta.shared::cta.b64 P1, [%0], 0, 0x989680;\n\t"
                "@P1 bra.uni D_%=;\n\t"
                "bra.uni W_%=;\n\t"
                "D_%=:\n\t}"
                :: "r"(mb) : "memory");
        }
        int4 cc = *(const int4*)(st_xy + 4 * threadIdx.x);
        float2 dd = *(const float2*)(st_d + 2 * threadIdx.x);
        xs[0] = cc.x; ys[0] = cc.y; xs[1] = cc.z; ys[1] = cc.w;
        C_[0] = (dd.x - 0.008f) * Kc;
        C_[1] = (dd.y - 0.008f) * Kc;
    } else {
        if (has2) {
            int4   cc = __ldg((const int4*)(xy + 2 * idx0));
            float2 dd = __ldg((const float2*)(depth + idx0));
            xs[0] = cc.x; ys[0] = cc.y; xs[1] = cc.z; ys[1] = cc.w;
            C_[0] = (dd.x - 0.008f) * Kc;
            C_[1] = (dd.y - 0.008f) * Kc;
        } else {
            int2 cc = __ldg((const int2*)(xy + 2 * idx0));
            xs[0] = cc.x; ys[0] = cc.y; xs[1] = 0; ys[1] = 0;
            C_[0] = (__ldg(depth + idx0) - 0.008f) * Kc;
            C_[1] = 0.0f;
        }
    }

    float acc[2] = {0.0f, 0.0f};

    if ((S & 3) == 0 && has2) {
        // ---- fast path: rows 16B-aligned ----
        const float* rows[2][3];
        bool d2_[2], d1_[2], lo_[2], hi_[2], nq_[2];

#pragma unroll
        for (int p = 0; p < 2; ++p) {
            const int idx = idx0 + p;
            const int b   = b0v + (idx >= lim);
            const int x = xs[p], y = ys[p];
            const int ym = max(y - 1, 0);
            const int yp = min(y + 1, S - 1);
            const int xi = min(max(x, 1), S - 2);
            const int c0 = xi - 1;
            const int e16 = c0 & ~3;
            const int d   = c0 - e16;          // 0..3
            nq_[p] = (d >= 2);
            d2_[p] = (d & 2) != 0;
            d1_[p] = (d & 1) != 0;
            lo_[p] = (x < 1);
            hi_[p] = (x > S - 2);
            const float* zb = zbuf + (size_t)b * (size_t)SS;
            rows[p][0] = zb + (size_t)(unsigned)ym * (unsigned)S + e16;
            rows[p][1] = zb + (size_t)(unsigned)y  * (unsigned)S + e16;
            rows[p][2] = zb + (size_t)(unsigned)yp * (unsigned)S + e16;
        }

        // Issue all gathers before any consumption (max MLP).
        float4 P[2][3];
        float2 Q[2][3];
#pragma unroll
        for (int p = 0; p < 2; ++p)
#pragma unroll
            for (int r = 0; r < 3; ++r)
                P[p][r] = __ldg((const float4*)rows[p][r]);
#pragma unroll
        for (int p = 0; p < 2; ++p)
#pragma unroll
            for (int r = 0; r < 3; ++r) {
                Q[p][r] = make_float2(0.0f, 0.0f);
                if (nq_[p]) Q[p][r] = __ldg((const float2*)(rows[p][r] + 4));
            }

#pragma unroll
        for (int p = 0; p < 2; ++p) {
            const bool d2 = d2_[p], d1 = d1_[p], lo = lo_[p], hi = hi_[p];
            const float C = C_[p];
            float pv[9];
#pragma unroll
            for (int r = 0; r < 3; ++r) {
                float g0 = d2 ? P[p][r].z : P[p][r].x;
                float g1 = d2 ? P[p][r].w : P[p][r].y;
                float g2 = d2 ? Q[p][r].x : P[p][r].z;
                float g3 = d2 ? Q[p][r].y : P[p][r].w;
                float t0 = d1 ? g1 : g0;
                float t1 = d1 ? g2 : g1;
                float t2 = d1 ? g3 : g2;
                float vl = hi ? t1 : t0;
                float vm = lo ? t0 : (hi ? t2 : t1);
                float vr = lo ? t1 : t2;
                pv[3 * r + 0] = pval(vl, C, Kc);
                pv[3 * r + 1] = pval(vm, C, Kc);
                pv[3 * r + 2] = pval(vr, C, Kc);
            }
            acc[p] = quad_sum(pv[0], pv[1], pv[2], pv[3])
                   + quad_sum(pv[4], pv[5], pv[6], pv[7])
                   + rcpf(pv[8]);
        }
        float2 o = make_float2(acc[0] * (1.0f / 9.0f), acc[1] * (1.0f / 9.0f));
        *(float2*)(out + idx0) = o;
    } else {
        // ---- generic path ----
        for (int p = 0; p < 2; ++p) {
            const int idx = idx0 + p;
            if (p == 1 && !has2) break;
            const int b = b0v + (idx >= lim);
            const int x = xs[p], y = ys[p];
            const int xm = max(x - 1, 0), xp = min(x + 1, S - 1);
            const int ym = max(y - 1, 0), yp = min(y + 1, S - 1);
            const float* zb = zbuf + (size_t)b * (size_t)SS;
            const float C = C_[p];
            float a = 0.0f;
            int yy[3] = {ym, y, yp};
            for (int r = 0; r < 3; ++r) {
                const float* rr = zb + (size_t)(unsigned)yy[r] * (unsigned)S;
                a += rcpf(pval(__ldg(rr + xm), C, Kc));
                a += rcpf(pval(__ldg(rr + x ), C, Kc));
                a += rcpf(pval(__ldg(rr + xp), C, Kc));
            }
            out[idx] = a * (1.0f / 9.0f);
        }
    }
}

extern "C" void kernel_launch(void* const* d_in, const int* in_sizes, int n_in,
                              void* d_out, int out_size) {
    const float* zbuf   = (const float*)d_in[0];
    const float* depth  = (const float*)d_in[1];
    const int*   xy     = (const int*)  d_in[2];
    const int*   imsz   = (const int*)  d_in[3];
    float*       out    = (float*)d_out;

    const int total      = in_sizes[1];
    const int zbuf_total = in_sizes[0];

    const int blocks = (total + PX_PER_BLOCK - 1) / PX_PER_BLOCK;
    shadow_pcf2t_kernel<<<blocks, 256>>>(zbuf, depth, xy, imsz, out,
                                         total, zbuf_total);
}